// round 3
// baseline (speedup 1.0000x reference)
#include <cuda_runtime.h>
#include <math.h>

#define N  512
#define NB 128

__device__ double   g_partial[NB];
__device__ unsigned g_count;   // zero-initialized; reset by last block each launch

// f = concat(features[:,0,:], features[:,1,:]) ; features is [256,2,256] row-major
__device__ __forceinline__ int fbase(int i){
  return (i < 256) ? (i * 512) : ((i - 256) * 512 + 256);
}

__global__ void __launch_bounds__(256, 1) rnc_fused(const float* __restrict__ feat,
                                                    const float* __restrict__ labels,
                                                    float* __restrict__ out)
{
  __shared__ float  s_sq[4][N];     // squared distances, 4 rows
  __shared__ float  s_Ls[N];        // sorted (duplicated) labels
  __shared__ int    s_perm[N];      // sorted pos -> original row
  __shared__ float  s_lab[256];
  __shared__ double s_P[N];         // inclusive prefix of exp in sorted order
  __shared__ double s_wsum[8];
  __shared__ double s_red[8];
  __shared__ bool   s_last;

  const int t = threadIdx.x, lane = t & 31, w = t >> 5;
  const int i0 = blockIdx.x * 4;

  // ---- per-block label rank sort (cheap, replaces prep kernel) ----
  s_lab[t] = labels[t];
  __syncthreads();
  {
    const float v = s_lab[t];
    int r = 0;
#pragma unroll 8
    for (int j = 0; j < 256; j++){
      float u = s_lab[j];
      r += (u < v) | ((u == v) & (j < t));
    }
    s_Ls[2*r]   = v;  s_Ls[2*r+1]   = v;
    s_perm[2*r] = t;  s_perm[2*r+1] = t + 256;
  }

  // ---- phase A: squared distances for 4 rows (warp-per-column, float4) ----
  float4 fir[4][2];
#pragma unroll
  for (int r = 0; r < 4; r++){
    const float4* fr = (const float4*)(feat + fbase(i0 + r));
    fir[r][0] = fr[lane];
    fir[r][1] = fr[lane + 32];
  }

  for (int j = w; j < N; j += 8){
    const float4* fj = (const float4*)(feat + fbase(j));
    const float4 v0 = fj[lane];
    const float4 v1 = fj[lane + 32];
    float a[4];
#pragma unroll
    for (int r = 0; r < 4; r++){
      const float4 p = fir[r][0], q = fir[r][1];
      float d0 = p.x - v0.x, d1 = p.y - v0.y, d2 = p.z - v0.z, d3 = p.w - v0.w;
      float acc = d0*d0;
      acc = fmaf(d1, d1, acc); acc = fmaf(d2, d2, acc); acc = fmaf(d3, d3, acc);
      d0 = q.x - v1.x; d1 = q.y - v1.y; d2 = q.z - v1.z; d3 = q.w - v1.w;
      acc = fmaf(d0, d0, acc); acc = fmaf(d1, d1, acc);
      acc = fmaf(d2, d2, acc); acc = fmaf(d3, d3, acc);
      a[r] = acc;
    }
#pragma unroll
    for (int o = 16; o; o >>= 1){
      a[0] += __shfl_xor_sync(0xffffffffu, a[0], o);
      a[1] += __shfl_xor_sync(0xffffffffu, a[1], o);
      a[2] += __shfl_xor_sync(0xffffffffu, a[2], o);
      a[3] += __shfl_xor_sync(0xffffffffu, a[3], o);
    }
    if (lane == 0){
      s_sq[0][j] = a[0]; s_sq[1][j] = a[1];
      s_sq[2][j] = a[2]; s_sq[3][j] = a[3];
    }
  }
  __syncthreads();

  // ---- phase B: per-row loss via sorted-label intervals ----
  double block_acc = 0.0;

  for (int r = 0; r < 4; r++){
    const int i = i0 + r;
    const float li = s_lab[i & 255];

    // gather distances & exps in sorted-label order (diagonal: sq==0 -> d=0, e=1)
    const int x0 = 2*t, x1 = 2*t + 1;
    const int j0 = s_perm[x0], j1 = s_perm[x1];
    const float d0 = sqrtf(s_sq[r][j0]);
    const float d1 = sqrtf(s_sq[r][j1]);
    const float e0 = expf(-0.5f * d0);     // logits_max == 0, TEMP = 2
    const float e1 = expf(-0.5f * d1);

    // 2-barrier warp-shuffle inclusive scan over 512 exps (double)
    double sc = (double)e0 + (double)e1;
#pragma unroll
    for (int o = 1; o < 32; o <<= 1){
      double v = __shfl_up_sync(0xffffffffu, sc, o);
      if (lane >= o) sc += v;
    }
    if (lane == 31) s_wsum[w] = sc;
    __syncthreads();
    if (w == 0 && lane < 8){
      double v = s_wsum[lane];
#pragma unroll
      for (int o = 1; o < 8; o <<= 1){
        double u = __shfl_up_sync(0xffu, v, o);
        if (lane >= o) v += u;
      }
      s_wsum[lane] = v;
    }
    __syncthreads();
    const double woff = (w > 0) ? s_wsum[w - 1] : 0.0;
    const double p1 = woff + sc;
    s_P[x0] = p1 - (double)e1;
    s_P[x1] = p1;
    __syncthreads();
    const double total = s_P[N - 1];

    // il: first sorted pos with Ls >= li (Ls[il] == li exactly) — once per row
    int il;
    { int lo = 0, len = N;
      while (len){ int h = len >> 1, m = lo + h;
        if (s_Ls[m] < li){ lo = m + 1; len -= h + 1; } else len = h; }
      il = lo; }

    // two k's per thread; 4 fused binary-search chains for ILP
    const int k0 = t, k1 = t + 256;
    const float tk0 = fabsf(s_lab[k0 & 255] - li);
    const float tk1 = fabsf(s_lab[k1 & 255] - li);

    int a0 = 0, la0 = il + 1, c0 = il, lc0 = N - il;
    int a1 = 0, la1 = il + 1, c1 = il, lc1 = N - il;
#pragma unroll 1
    for (int s = 0; s < 10; s++){
      if (la0){ int h = la0 >> 1, m = a0 + h;
        if (!(fabsf(s_Ls[m] - li) < tk0)){ a0 = m + 1; la0 -= h + 1; } else la0 = h; }
      if (lc0){ int h = lc0 >> 1, m = c0 + h;
        if ( (fabsf(s_Ls[m] - li) < tk0)){ c0 = m + 1; lc0 -= h + 1; } else lc0 = h; }
      if (la1){ int h = la1 >> 1, m = a1 + h;
        if (!(fabsf(s_Ls[m] - li) < tk1)){ a1 = m + 1; la1 -= h + 1; } else la1 = h; }
      if (lc1){ int h = lc1 >> 1, m = c1 + h;
        if ( (fabsf(s_Ls[m] - li) < tk1)){ c1 = m + 1; lc1 -= h + 1; } else lc1 = h; }
    }

    double lsum = 0.0;
    if (k0 != i){
      double neg = (tk0 == 0.f) ? (total - 1.0)
                 : (total - (s_P[c0 - 1] - (a0 > 0 ? s_P[a0 - 1] : 0.0)));
      lsum += (double)logf((float)neg);
    }
    if (k1 != i){
      double neg = (tk1 == 0.f) ? (total - 1.0)
                 : (total - (s_P[c1 - 1] - (a1 > 0 ? s_P[a1 - 1] : 0.0)));
      lsum += (double)logf((float)neg);
    }

    block_acc += 0.5 * ((double)d0 + (double)d1) + lsum;
    __syncthreads();   // protect s_P / s_wsum before next row
  }

  // ---- block reduction ----
#pragma unroll
  for (int o = 16; o; o >>= 1)
    block_acc += __shfl_xor_sync(0xffffffffu, block_acc, o);
  if (lane == 0) s_red[w] = block_acc;
  __syncthreads();
  if (w == 0){
    double v = (lane < 8) ? s_red[lane] : 0.0;
#pragma unroll
    for (int o = 4; o; o >>= 1) v += __shfl_xor_sync(0xffffffffu, v, o);
    if (lane == 0){
      g_partial[blockIdx.x] = v;
      __threadfence();
      unsigned rr = atomicAdd(&g_count, 1u);
      s_last = (rr == NB - 1);
    }
  }
  __syncthreads();

  // ---- last block: deterministic fixed-tree final reduce ----
  if (s_last){
    double v = (t < NB) ? *((volatile double*)&g_partial[t]) : 0.0;
#pragma unroll
    for (int o = 16; o; o >>= 1)
      v += __shfl_xor_sync(0xffffffffu, v, o);
    if (lane == 0) s_red[w] = v;
    __syncthreads();
    if (w == 0){
      double u = (lane < 8) ? s_red[lane] : 0.0;
#pragma unroll
      for (int o = 4; o; o >>= 1) u += __shfl_xor_sync(0xffffffffu, u, o);
      if (lane == 0){
        out[0] = (float)(u / (512.0 * 511.0));   // 1 / (n*(n-1))
        g_count = 0;                              // reset for next graph replay
      }
    }
  }
}

extern "C" void kernel_launch(void* const* d_in, const int* in_sizes, int n_in,
                              void* d_out, int out_size)
{
  const float* feat   = (const float*)d_in[0];   // [256, 2, 256] fp32
  const float* labels = (const float*)d_in[1];   // [256, 1] fp32
  float* out = (float*)d_out;                    // scalar fp32

  rnc_fused<<<NB, 256>>>(feat, labels, out);
}

// round 4
// speedup vs baseline: 1.3701x; 1.3701x over previous
#include <cuda_runtime.h>
#include <math.h>

#define N   512
#define NB  128
#define TPB 512
#define BST 514     // B tile row stride (floats): conflict-free STS + aligned float2 LDS

typedef unsigned long long ull;

__device__ double   g_partial[NB];
__device__ unsigned g_count;   // zero-init; reset by last block each launch

struct SmemA {
  float  B[2][16][BST];   // double-buffered [d][j] tile, 65792 B
  float2 fid[4][256];     // block's 4 rows, duplicated {v,v} for f32x2
};
struct SmemT {
  union { SmemA a; double P[4][512]; } u;   // P overlays B (phase-disjoint)
  float2 sq[4][256];      // squared distances (flat float[512] per row)
  float  Ls[N];
  int    perm[N];
  float  lab[256];
  float2 nrm[256];        // column norms (flat float[512])
  double gw[4][4];
  double red[16];
  int    lastf;
};

__device__ __forceinline__ int fbase(int i){
  return (i < 256) ? (i * 512) : ((i - 256) * 512 + 256);
}
__device__ __forceinline__ void fma2(ull &acc, ull a, ull b){
  asm("fma.rn.f32x2 %0, %1, %2, %0;" : "+l"(acc) : "l"(a), "l"(b));
}
__device__ __forceinline__ float2 u2f(ull x){
  float2 f; asm("mov.b64 {%0,%1}, %2;" : "=f"(f.x), "=f"(f.y) : "l"(x)); return f;
}

__device__ __forceinline__ void load_chunk(SmemT& S, int buf, int ct, int t,
                                           const float* __restrict__ feat){
  const int u4 = t & 3, r0 = t >> 2;
#pragma unroll
  for (int p = 0; p < 4; p++){
    const int row = r0 + 128 * p;
    const float4 v = *(const float4*)(feat + fbase(row) + 16 * ct + 4 * u4);
    S.u.a.B[buf][4*u4 + 0][row] = v.x;
    S.u.a.B[buf][4*u4 + 1][row] = v.y;
    S.u.a.B[buf][4*u4 + 2][row] = v.z;
    S.u.a.B[buf][4*u4 + 3][row] = v.w;
  }
}

__global__ void __launch_bounds__(TPB) rnc_fused(const float* __restrict__ feat,
                                                 const float* __restrict__ labels,
                                                 float* __restrict__ out)
{
  extern __shared__ char smem_raw[];
  SmemT& S = *(SmemT*)smem_raw;

  const int t = threadIdx.x, lane = t & 31, wid = t >> 5;
  const int i0 = blockIdx.x * 4;
  const int h  = t >> 8;        // row half: rows 2h, 2h+1
  const int jp = t & 255;       // j-pair index (j = 2jp, 2jp+1)

  if (t < 256) S.lab[t] = labels[t];
  // block's 4 rows, duplicated for packed math
#pragma unroll
  for (int e = t; e < 1024; e += TPB){
    const int r = e >> 8, d = e & 255;
    const float v = feat[fbase(i0 + r) + d];
    S.u.a.fid[r][d] = make_float2(v, v);
  }
  load_chunk(S, 0, 0, t, feat);
  __syncthreads();

  // ---- label rank sort (half the threads; others proceed to compute) ----
  if (t < 256){
    const float v = S.lab[t];
    int r = 0;
#pragma unroll 8
    for (int j = 0; j < 256; j++){
      const float w = S.lab[j];
      r += (w < v) | ((w == v) & (j < t));
    }
    S.Ls[2*r] = v;  S.Ls[2*r+1] = v;
    S.perm[2*r] = t; S.perm[2*r+1] = t + 256;
  }

  // ---- phase A: Gram accumulation, packed f32x2, double-buffered tiles ----
  ull acc0 = 0, acc1 = 0, nrmreg = 0;
#pragma unroll 1
  for (int ct = 0; ct < 16; ct++){
    const int buf = ct & 1;
    if (ct + 1 < 16) load_chunk(S, buf ^ 1, ct + 1, t, feat);
#pragma unroll
    for (int d2 = 0; d2 < 8; d2++){
      const ull b0 = *(const ull*)&S.u.a.B[buf][2*d2    ][2*jp];
      const ull b1 = *(const ull*)&S.u.a.B[buf][2*d2 + 1][2*jp];
      const ulonglong2 fa = *(const ulonglong2*)&S.u.a.fid[2*h    ][ct*16 + 2*d2];
      const ulonglong2 fb = *(const ulonglong2*)&S.u.a.fid[2*h + 1][ct*16 + 2*d2];
      fma2(acc0, fa.x, b0); fma2(acc0, fa.y, b1);
      fma2(acc1, fb.x, b0); fma2(acc1, fb.y, b1);
      if (h == 0){ fma2(nrmreg, b0, b0); fma2(nrmreg, b1, b1); }
    }
    __syncthreads();
  }

  // ---- epilogue: sq = ni + nj - 2*g ----
  if (h == 0) S.nrm[jp] = u2f(nrmreg);
  __syncthreads();
  {
    const float2 njv = u2f(*(const ull*)&S.nrm[jp]);
    int r = 2*h;
    float ni = ((const float*)S.nrm)[i0 + r];
    float2 gv = u2f(acc0);
    S.sq[r][jp] = make_float2(ni + njv.x - 2.f*gv.x, ni + njv.y - 2.f*gv.y);
    r = 2*h + 1;
    ni = ((const float*)S.nrm)[i0 + r];
    gv = u2f(acc1);
    S.sq[r][jp] = make_float2(ni + njv.x - 2.f*gv.x, ni + njv.y - 2.f*gv.y);
  }
  __syncthreads();

  // ---- phase B: 4 rows concurrently, 128 threads per row ----
  const int gg = t >> 7;          // row group 0..3
  const int u  = t & 127;
  const int wl = (t >> 5) & 3;    // warp within group
  const int i  = i0 + gg;
  const float li = S.lab[i & 255];
  const float* sqrow = (const float*)S.sq[gg];

  double e[4]; double dsum = 0.0;
#pragma unroll
  for (int q = 0; q < 4; q++){
    const int x = 4*u + q;
    const int j = S.perm[x];
    float d, ev;
    if (j == i){ d = 0.f; ev = 1.f; }
    else { d = sqrtf(fmaxf(sqrow[j], 0.f)); ev = expf(-0.5f * d); }   // logits_max==0, TEMP=2
    dsum += (double)d; e[q] = (double)ev;
  }
  const double p1 = e[0], p2 = p1 + e[1], p3 = p2 + e[2], p4 = p3 + e[3];

  double sc = p4;                              // warp inclusive scan over thread sums
#pragma unroll
  for (int o = 1; o < 32; o <<= 1){
    const double v = __shfl_up_sync(0xffffffffu, sc, o);
    if (lane >= o) sc += v;
  }
  if (lane == 31) S.gw[gg][wl] = sc;
  __syncthreads();
  double woff = 0.0;
#pragma unroll
  for (int w2 = 0; w2 < 3; w2++) if (w2 < wl) woff += S.gw[gg][w2];
  const double base = woff + sc - p4;
  S.u.P[gg][4*u + 0] = base + p1;
  S.u.P[gg][4*u + 1] = base + p2;
  S.u.P[gg][4*u + 2] = base + p3;
  S.u.P[gg][4*u + 3] = base + p4;
  __syncthreads();
  const double* Pr = S.u.P[gg];
  const double total = Pr[N - 1];

  // il: first sorted pos with Ls >= li
  int lo = 0, len = N;
  while (len){ const int hh = len >> 1, m = lo + hh;
    if (S.Ls[m] < li){ lo = m + 1; len -= hh + 1; } else len = hh; }
  const int il = lo;

  int A[4], C[4], LA[4], LC[4], KK[4]; float TK[4];
#pragma unroll
  for (int kk = 0; kk < 4; kk++){
    const int k = u + 128*kk; KK[kk] = k;
    TK[kk] = fabsf(S.lab[k & 255] - li);
    A[kk] = 0; LA[kk] = il + 1; C[kk] = il; LC[kk] = N - il;
  }
#pragma unroll 1
  for (int s = 0; s < 10; s++){
#pragma unroll
    for (int kk = 0; kk < 4; kk++){
      if (LA[kk]){ const int hh = LA[kk] >> 1, m = A[kk] + hh;
        if (!(fabsf(S.Ls[m] - li) < TK[kk])){ A[kk] = m + 1; LA[kk] -= hh + 1; } else LA[kk] = hh; }
      if (LC[kk]){ const int hh = LC[kk] >> 1, m = C[kk] + hh;
        if ( (fabsf(S.Ls[m] - li) < TK[kk])){ C[kk] = m + 1; LC[kk] -= hh + 1; } else LC[kk] = hh; }
    }
  }
  double lsum = 0.0;
#pragma unroll
  for (int kk = 0; kk < 4; kk++){
    if (KK[kk] == i) continue;
    const double neg = (TK[kk] == 0.f) ? (total - 1.0)
        : (total - (Pr[C[kk] - 1] - (A[kk] > 0 ? Pr[A[kk] - 1] : 0.0)));
    lsum += (double)logf((float)neg);
  }

  // ---- block reduce + cross-block deterministic reduce ----
  double acc = 0.5 * dsum + lsum;
#pragma unroll
  for (int o = 16; o; o >>= 1) acc += __shfl_xor_sync(0xffffffffu, acc, o);
  if (lane == 0) S.red[wid] = acc;
  __syncthreads();
  if (wid == 0){
    double v = (lane < 16) ? S.red[lane] : 0.0;
#pragma unroll
    for (int o = 8; o; o >>= 1) v += __shfl_xor_sync(0xffffffffu, v, o);
    if (lane == 0){
      g_partial[blockIdx.x] = v;
      __threadfence();
      S.lastf = (atomicAdd(&g_count, 1u) == NB - 1);
    }
  }
  __syncthreads();

  if (S.lastf){
    double v = (t < NB) ? *((volatile double*)&g_partial[t]) : 0.0;
#pragma unroll
    for (int o = 16; o; o >>= 1) v += __shfl_xor_sync(0xffffffffu, v, o);
    if (lane == 0) S.red[wid] = v;
    __syncthreads();
    if (wid == 0){
      double s = (lane < 16) ? S.red[lane] : 0.0;
#pragma unroll
      for (int o = 8; o; o >>= 1) s += __shfl_xor_sync(0xffffffffu, s, o);
      if (lane == 0){
        out[0] = (float)(s / (512.0 * 511.0));
        g_count = 0;   // reset for next graph replay
      }
    }
  }
}

extern "C" void kernel_launch(void* const* d_in, const int* in_sizes, int n_in,
                              void* d_out, int out_size)
{
  const float* feat   = (const float*)d_in[0];   // [256, 2, 256] fp32
  const float* labels = (const float*)d_in[1];   // [256, 1] fp32
  float* out = (float*)d_out;                    // scalar fp32

  cudaFuncSetAttribute(rnc_fused, cudaFuncAttributeMaxDynamicSharedMemorySize,
                       (int)sizeof(SmemT));
  rnc_fused<<<NB, TPB, sizeof(SmemT)>>>(feat, labels, out);
}

// round 5
// speedup vs baseline: 1.7154x; 1.2520x over previous
#include <cuda_runtime.h>
#include <math.h>

#define N   512
#define RT  32      // rows per GEMM block
#define JT  64      // cols (js) per GEMM block
#define BUP 66      // Bu row stride in ulls (pad: conflict control)

typedef unsigned long long ull;

__device__ float    g_sq[N * N];    // squared pairwise distances
__device__ float    g_Ls[N];        // sorted duplicated labels
__device__ int      g_perm[N];      // sorted pos -> original row
__device__ double   g_partial[N];
__device__ unsigned g_count;        // zero-init; reset each launch by last loss block

// f = concat(features[:,0,:], features[:,1,:]) ; features is [256,2,256] row-major
__device__ __forceinline__ int fbase(int i){
  return (i < 256) ? (i * 512) : ((i - 256) * 512 + 256);
}
__device__ __forceinline__ void fma2(ull &acc, ull a, ull b){
  asm("fma.rn.f32x2 %0, %1, %2, %0;" : "+l"(acc) : "l"(a), "l"(b));
}
__device__ __forceinline__ float2 u2f(ull x){
  float2 f; asm("mov.b64 {%0,%1}, %2;" : "=f"(f.x), "=f"(f.y) : "l"(x)); return f;
}
__device__ __forceinline__ ull f2u(float a, float b){
  ull r; asm("mov.b64 %0, {%1,%2};" : "=l"(r) : "f"(a), "f"(b)); return r;
}

struct GSmem {
  ull   Au[RT][128];     // a-tile [row][k-pair]        32 KB
  ull   Bu[128][BUP];    // b-tile [k-pair][j], padded  ~67.6 KB
  float nrmA[RT];
  float nrmB[JT];
  float lab[256];
};

// ---------------- kernel 1: 32x64 Gram tiles -> g_sq (+ block 0: label sort) ----------
__global__ void __launch_bounds__(256) dist_kernel(const float* __restrict__ feat,
                                                   const float* __restrict__ labels)
{
  extern __shared__ char raw[];
  GSmem& S = *(GSmem*)raw;

  const int t = threadIdx.x, lane = t & 31, w = t >> 5;
  const int bj = blockIdx.x & 7, bi = blockIdx.x >> 3;
  const int r0 = bi * RT, j0 = bj * JT;

  if (t < 256) S.lab[t] = labels[t];

  // ---- load A tile [32 rows][256 k] natural layout (k-pairs in ull halves) ----
#pragma unroll
  for (int p = 0; p < 8; p++){
    const int idx = t + 256 * p;          // 0..2047
    const int row = idx >> 6, c = idx & 63;
    const float4 v = *(const float4*)(feat + fbase(r0 + row) + 4 * c);
    ((float4*)S.Au[row])[c] = v;
  }

  // ---- load B tile transposed: Bu[d2][j] = {f[j][2d2], f[j][2d2+1]} ----
  {
    const int j = t >> 2, u = t & 3;
#pragma unroll
    for (int q = 0; q < 16; q++){
      const float4 v = *(const float4*)(feat + fbase(j0 + j) + 16 * q + 4 * u);
      const int d2 = 8 * q + 2 * u;
      S.Bu[d2    ][j] = f2u(v.x, v.y);
      S.Bu[d2 + 1][j] = f2u(v.z, v.w);
    }
  }
  __syncthreads();

  // ---- block 0 additionally rank-sorts the labels (global) ----
  if (blockIdx.x == 0 && t < 256){
    const float v = S.lab[t];
    int r = 0;
#pragma unroll 8
    for (int j = 0; j < 256; j++){
      const float u = S.lab[j];
      r += (u < v) | ((u == v) & (j < t));
    }
    g_Ls[2*r] = v;  g_Ls[2*r+1] = v;
    g_perm[2*r] = t; g_perm[2*r+1] = t + 256;
  }

  // ---- norms for this block's rows (t<32) and js (32<=t<96) ----
  if (t < 32){
    ull a0 = 0, a1 = 0, a2 = 0, a3 = 0;
#pragma unroll 8
    for (int d2 = 0; d2 < 128; d2 += 4){
      fma2(a0, S.Au[t][d2],   S.Au[t][d2]);
      fma2(a1, S.Au[t][d2+1], S.Au[t][d2+1]);
      fma2(a2, S.Au[t][d2+2], S.Au[t][d2+2]);
      fma2(a3, S.Au[t][d2+3], S.Au[t][d2+3]);
    }
    const float2 f0 = u2f(a0), f1 = u2f(a1), f2 = u2f(a2), f3 = u2f(a3);
    S.nrmA[t] = (f0.x+f0.y) + (f1.x+f1.y) + (f2.x+f2.y) + (f3.x+f3.y);
  } else if (t < 96){
    const int jn = t - 32;
    ull a0 = 0, a1 = 0, a2 = 0, a3 = 0;
#pragma unroll 8
    for (int d2 = 0; d2 < 128; d2 += 4){
      fma2(a0, S.Bu[d2  ][jn], S.Bu[d2  ][jn]);
      fma2(a1, S.Bu[d2+1][jn], S.Bu[d2+1][jn]);
      fma2(a2, S.Bu[d2+2][jn], S.Bu[d2+2][jn]);
      fma2(a3, S.Bu[d2+3][jn], S.Bu[d2+3][jn]);
    }
    const float2 f0 = u2f(a0), f1 = u2f(a1), f2 = u2f(a2), f3 = u2f(a3);
    S.nrmB[jn] = (f0.x+f0.y) + (f1.x+f1.y) + (f2.x+f2.y) + (f3.x+f3.y);
  }

  // ---- main: thread-tile 4 rows x 2 js, warp w -> rows 4w..4w+3, lane -> js 2lane,2lane+1
  ull acc[4][2] = {{0,0},{0,0},{0,0},{0,0}};
  const int jb = 2 * lane;
#pragma unroll 4
  for (int d2 = 0; d2 < 128; d2 += 2){
    const ulonglong2 b0 = *(const ulonglong2*)&S.Bu[d2    ][jb];  // {j0,j1} @ kpair d2
    const ulonglong2 b1 = *(const ulonglong2*)&S.Bu[d2 + 1][jb];  // {j0,j1} @ kpair d2+1
#pragma unroll
    for (int rr = 0; rr < 4; rr++){
      const ulonglong2 av = *(const ulonglong2*)&S.Au[4*w + rr][d2];  // broadcast
      fma2(acc[rr][0], av.x, b0.x);  fma2(acc[rr][1], av.x, b0.y);
      fma2(acc[rr][0], av.y, b1.x);  fma2(acc[rr][1], av.y, b1.y);
    }
  }
  __syncthreads();   // norms visible

  // ---- epilogue: sq = ni + nj - 2g ----
  const float nj0 = S.nrmB[jb], nj1 = S.nrmB[jb + 1];
#pragma unroll
  for (int rr = 0; rr < 4; rr++){
    const float ni = S.nrmA[4*w + rr];
    const float2 g0 = u2f(acc[rr][0]);
    const float2 g1 = u2f(acc[rr][1]);
    float2 o;
    o.x = ni + nj0 - 2.f * (g0.x + g0.y);
    o.y = ni + nj1 - 2.f * (g1.x + g1.y);
    *(float2*)&g_sq[(r0 + 4*w + rr) * N + j0 + jb] = o;
  }
}

// ---------------- kernel 2: per-row loss (512 blocks, one row each) ----------------
__global__ void __launch_bounds__(256) loss_kernel(const float* __restrict__ labels,
                                                   float* __restrict__ out)
{
  __shared__ float  s_Ls[N];
  __shared__ int    s_perm[N];
  __shared__ float  s_sq[N];
  __shared__ float  s_lab[256];
  __shared__ double s_P[N];
  __shared__ double s_wsum[8];
  __shared__ double s_red[8];
  __shared__ bool   s_last;

  const int t = threadIdx.x, lane = t & 31, w = t >> 5;
  const int i = blockIdx.x;

  if (t < 256) s_lab[t] = labels[t];
  for (int x = t; x < N; x += 256){
    s_Ls[x] = g_Ls[x];
    s_perm[x] = g_perm[x];
    s_sq[x] = g_sq[i * N + x];
  }
  __syncthreads();

  const float li = s_lab[i & 255];

  // positions 2t, 2t+1 in sorted order
  const int x0 = 2*t, x1 = 2*t + 1;
  const int j0 = s_perm[x0], j1 = s_perm[x1];
  const float d0 = (j0 == i) ? 0.f : sqrtf(fmaxf(s_sq[j0], 0.f));
  const float d1 = (j1 == i) ? 0.f : sqrtf(fmaxf(s_sq[j1], 0.f));
  const float e0 = (j0 == i) ? 1.f : expf(-0.5f * d0);   // logits_max==0, TEMP=2
  const float e1 = (j1 == i) ? 1.f : expf(-0.5f * d1);

  // 2-barrier warp-shuffle inclusive scan over 512 exps (double)
  double sc = (double)e0 + (double)e1;
#pragma unroll
  for (int o = 1; o < 32; o <<= 1){
    const double v = __shfl_up_sync(0xffffffffu, sc, o);
    if (lane >= o) sc += v;
  }
  if (lane == 31) s_wsum[w] = sc;
  __syncthreads();
  if (w == 0 && lane < 8){
    double v = s_wsum[lane];
#pragma unroll
    for (int o = 1; o < 8; o <<= 1){
      const double u = __shfl_up_sync(0xffu, v, o);
      if (lane >= o) v += u;
    }
    s_wsum[lane] = v;
  }
  __syncthreads();
  const double woff = (w > 0) ? s_wsum[w - 1] : 0.0;
  const double p1 = woff + sc;
  s_P[x0] = p1 - (double)e1;
  s_P[x1] = p1;
  __syncthreads();
  const double total = s_P[N - 1];

  // il: first sorted pos with Ls >= li
  int lo = 0, len = N;
  while (len){ const int h = len >> 1, m = lo + h;
    if (s_Ls[m] < li){ lo = m + 1; len -= h + 1; } else len = h; }
  const int il = lo;

  // two k's per thread; 4 fused binary-search chains
  const int k0 = t, k1 = t + 256;
  const float tk0 = fabsf(s_lab[k0 & 255] - li);
  const float tk1 = fabsf(s_lab[k1 & 255] - li);
  int a0 = 0, la0 = il + 1, c0 = il, lc0 = N - il;
  int a1 = 0, la1 = il + 1, c1 = il, lc1 = N - il;
#pragma unroll 1
  for (int s = 0; s < 10; s++){
    if (la0){ const int h = la0 >> 1, m = a0 + h;
      if (!(fabsf(s_Ls[m] - li) < tk0)){ a0 = m + 1; la0 -= h + 1; } else la0 = h; }
    if (lc0){ const int h = lc0 >> 1, m = c0 + h;
      if ( (fabsf(s_Ls[m] - li) < tk0)){ c0 = m + 1; lc0 -= h + 1; } else lc0 = h; }
    if (la1){ const int h = la1 >> 1, m = a1 + h;
      if (!(fabsf(s_Ls[m] - li) < tk1)){ a1 = m + 1; la1 -= h + 1; } else la1 = h; }
    if (lc1){ const int h = lc1 >> 1, m = c1 + h;
      if ( (fabsf(s_Ls[m] - li) < tk1)){ c1 = m + 1; lc1 -= h + 1; } else lc1 = h; }
  }

  double lsum = 0.0;
  if (k0 != i){
    const double neg = (tk0 == 0.f) ? (total - 1.0)
        : (total - (s_P[c0 - 1] - (a0 > 0 ? s_P[a0 - 1] : 0.0)));
    lsum += (double)logf((float)neg);
  }
  if (k1 != i){
    const double neg = (tk1 == 0.f) ? (total - 1.0)
        : (total - (s_P[c1 - 1] - (a1 > 0 ? s_P[a1 - 1] : 0.0)));
    lsum += (double)logf((float)neg);
  }

  // row contribution: sum_j d_ij / TEMP + sum_k log(neg)
  double acc = 0.5 * ((double)d0 + (double)d1) + lsum;
#pragma unroll
  for (int o = 16; o; o >>= 1) acc += __shfl_xor_sync(0xffffffffu, acc, o);
  if (lane == 0) s_red[w] = acc;
  __syncthreads();
  if (w == 0){
    double v = (lane < 8) ? s_red[lane] : 0.0;
#pragma unroll
    for (int o = 4; o; o >>= 1) v += __shfl_xor_sync(0xffffffffu, v, o);
    if (lane == 0){
      g_partial[i] = v;
      __threadfence();
      s_last = (atomicAdd(&g_count, 1u) == N - 1);
    }
  }
  __syncthreads();

  // last block: deterministic fixed-tree final reduce over 512 partials
  if (s_last){
    double v = *((volatile double*)&g_partial[t])
             + *((volatile double*)&g_partial[t + 256]);
#pragma unroll
    for (int o = 16; o; o >>= 1) v += __shfl_xor_sync(0xffffffffu, v, o);
    if (lane == 0) s_red[w] = v;
    __syncthreads();
    if (w == 0){
      double s = (lane < 8) ? s_red[lane] : 0.0;
#pragma unroll
      for (int o = 4; o; o >>= 1) s += __shfl_xor_sync(0xffffffffu, s, o);
      if (lane == 0){
        out[0] = (float)(s / (512.0 * 511.0));   // 1 / (n*(n-1))
        g_count = 0;                              // reset for next graph replay
      }
    }
  }
}

extern "C" void kernel_launch(void* const* d_in, const int* in_sizes, int n_in,
                              void* d_out, int out_size)
{
  const float* feat   = (const float*)d_in[0];   // [256, 2, 256] fp32
  const float* labels = (const float*)d_in[1];   // [256, 1] fp32
  float* out = (float*)d_out;                    // scalar fp32

  cudaFuncSetAttribute(dist_kernel, cudaFuncAttributeMaxDynamicSharedMemorySize,
                       (int)sizeof(GSmem));
  dist_kernel<<<128, 256, sizeof(GSmem)>>>(feat, labels);
  loss_kernel<<<N, 256>>>(labels, out);
}

// round 6
// speedup vs baseline: 1.8509x; 1.0789x over previous
#include <cuda_runtime.h>
#include <math.h>

#define N    512
#define RT   32
#define JT   32
#define BUP2 33     // Bu row stride in ulls

typedef unsigned long long ull;

__device__ float    g_sq[N * N];
__device__ float    g_Ls[N];
__device__ int      g_perm[N];
__device__ double   g_partial[256];
__device__ unsigned g_count;     // zero-init; reset by last loss block each launch

__device__ __forceinline__ int fbase(int i){
  return (i < 256) ? (i * 512) : ((i - 256) * 512 + 256);
}
__device__ __forceinline__ void fma2(ull &acc, ull a, ull b){
  asm("fma.rn.f32x2 %0, %1, %2, %0;" : "+l"(acc) : "l"(a), "l"(b));
}
__device__ __forceinline__ float2 u2f(ull x){
  float2 f; asm("mov.b64 {%0,%1}, %2;" : "=f"(f.x), "=f"(f.y) : "l"(x)); return f;
}
__device__ __forceinline__ ull f2u(float a, float b){
  ull r; asm("mov.b64 %0, {%1,%2};" : "=l"(r) : "f"(a), "f"(b)); return r;
}
__device__ __forceinline__ float fsqrt_ap(float x){
  float r; asm("sqrt.approx.f32 %0, %1;" : "=f"(r) : "f"(x)); return r;
}
__device__ __forceinline__ float ex2_ap(float x){
  float r; asm("ex2.approx.f32 %0, %1;" : "=f"(r) : "f"(x)); return r;
}
__device__ __forceinline__ float lg2_ap(float x){
  float r; asm("lg2.approx.f32 %0, %1;" : "=f"(r) : "f"(x)); return r;
}

struct GSmem {
  ull   Au[RT][128];      // 32 KB
  ull   Bu[128][BUP2];    // ~33.8 KB
  float nrmA[RT];
  float nrmB[JT];
  float lab[256];
};

// ---------------- kernel 1: 32x32 Gram tiles -> g_sq (+ block 0: label sort) ----------
__global__ void __launch_bounds__(256) dist_kernel(const float* __restrict__ feat,
                                                   const float* __restrict__ labels)
{
  extern __shared__ char raw[];
  GSmem& S = *(GSmem*)raw;

  const int t = threadIdx.x, lane = t & 31, w = t >> 5;
  const int bj = blockIdx.x & 15, bi = blockIdx.x >> 4;
  const int r0 = bi * RT, j0 = bj * JT;

  if (t < 256) S.lab[t] = labels[t];

  // A tile [32 rows][256 k], natural layout (k-pairs in ull halves)
#pragma unroll
  for (int p = 0; p < 8; p++){
    const int idx = t + 256 * p;
    const int row = idx >> 6, c = idx & 63;
    ((float4*)S.Au[row])[c] = *(const float4*)(feat + fbase(r0 + row) + 4 * c);
  }
  // B tile transposed: Bu[d2][j] = {f[j][2d2], f[j][2d2+1]}
  {
    const int j = t >> 3, u = t & 7;
#pragma unroll
    for (int q = 0; q < 8; q++){
      const float4 v = *(const float4*)(feat + fbase(j0 + j) + 32 * q + 4 * u);
      const int d2 = 16 * q + 2 * u;
      S.Bu[d2    ][j] = f2u(v.x, v.y);
      S.Bu[d2 + 1][j] = f2u(v.z, v.w);
    }
  }
  __syncthreads();

  // block 0: global label rank sort
  if (blockIdx.x == 0 && t < 256){
    const float v = S.lab[t];
    int r = 0;
#pragma unroll 8
    for (int j = 0; j < 256; j++){
      const float u = S.lab[j];
      r += (u < v) | ((u == v) & (j < t));
    }
    g_Ls[2*r] = v;  g_Ls[2*r+1] = v;
    g_perm[2*r] = t; g_perm[2*r+1] = t + 256;
  }

  // norms
  if (t < 32){
    ull a0 = 0, a1 = 0;
#pragma unroll 16
    for (int d2 = 0; d2 < 128; d2 += 2){
      fma2(a0, S.Au[t][d2],   S.Au[t][d2]);
      fma2(a1, S.Au[t][d2+1], S.Au[t][d2+1]);
    }
    const float2 f0 = u2f(a0), f1 = u2f(a1);
    S.nrmA[t] = (f0.x + f0.y) + (f1.x + f1.y);
  } else if (t < 64){
    const int jn = t - 32;
    ull a0 = 0, a1 = 0;
#pragma unroll 16
    for (int d2 = 0; d2 < 128; d2 += 2){
      fma2(a0, S.Bu[d2  ][jn], S.Bu[d2  ][jn]);
      fma2(a1, S.Bu[d2+1][jn], S.Bu[d2+1][jn]);
    }
    const float2 f0 = u2f(a0), f1 = u2f(a1);
    S.nrmB[jn] = (f0.x + f0.y) + (f1.x + f1.y);
  }

  // main: warp w -> rows 4w..4w+3, lane -> j = lane
  ull acc[4] = {0, 0, 0, 0};
#pragma unroll 4
  for (int d2 = 0; d2 < 128; d2 += 2){
    const ull b0 = S.Bu[d2    ][lane];
    const ull b1 = S.Bu[d2 + 1][lane];
#pragma unroll
    for (int rr = 0; rr < 4; rr++){
      const ulonglong2 av = *(const ulonglong2*)&S.Au[4*w + rr][d2];  // broadcast
      fma2(acc[rr], av.x, b0);
      fma2(acc[rr], av.y, b1);
    }
  }
  __syncthreads();   // norms visible

  const float nj = S.nrmB[lane];
#pragma unroll
  for (int rr = 0; rr < 4; rr++){
    const float ni = S.nrmA[4*w + rr];
    const float2 g = u2f(acc[rr]);
    g_sq[(r0 + 4*w + rr) * N + j0 + lane] = ni + nj - 2.f * (g.x + g.y);
  }
}

// -------- kernel 2: loss; block b handles rows b and b+256 (identical labels) --------
__global__ void __launch_bounds__(256) loss_kernel(const float* __restrict__ labels,
                                                   float* __restrict__ out)
{
  __shared__ float  s_Ls[N];
  __shared__ int    s_perm[N];
  __shared__ float  s_lab[256];
  __shared__ float  s_sq0[N], s_sq1[N];
  __shared__ double s_P0[N], s_P1[N];
  __shared__ double s_w0[8], s_w1[8];
  __shared__ double s_red[8];
  __shared__ bool   s_last;

  const int t = threadIdx.x, lane = t & 31, w = t >> 5;
  const int i0 = blockIdx.x, i1 = blockIdx.x + 256;

  s_lab[t] = labels[t];
  for (int x = t; x < N; x += 256){
    s_Ls[x]   = g_Ls[x];
    s_perm[x] = g_perm[x];
    s_sq0[x]  = g_sq[i0 * N + x];
    s_sq1[x]  = g_sq[i1 * N + x];
  }
  __syncthreads();

  const float li = s_lab[i0];
  const float KE = -0.72134752044448170f;   // -0.5 * log2(e)
  const float LN2 = 0.69314718055994531f;

  // positions 2t, 2t+1 in sorted order; both rows
  const int x0 = 2*t, x1 = 2*t + 1;
  const int j0 = s_perm[x0], j1 = s_perm[x1];

  const float d00 = (j0 == i0) ? 0.f : fsqrt_ap(fmaxf(s_sq0[j0], 0.f));
  const float d01 = (j1 == i0) ? 0.f : fsqrt_ap(fmaxf(s_sq0[j1], 0.f));
  const float d10 = (j0 == i1) ? 0.f : fsqrt_ap(fmaxf(s_sq1[j0], 0.f));
  const float d11 = (j1 == i1) ? 0.f : fsqrt_ap(fmaxf(s_sq1[j1], 0.f));
  const float e00 = (j0 == i0) ? 1.f : ex2_ap(KE * d00);
  const float e01 = (j1 == i0) ? 1.f : ex2_ap(KE * d01);
  const float e10 = (j0 == i1) ? 1.f : ex2_ap(KE * d10);
  const float e11 = (j1 == i1) ? 1.f : ex2_ap(KE * d11);

  // two interleaved warp-shuffle inclusive scans (double)
  double sc0 = (double)e00 + (double)e01;
  double sc1 = (double)e10 + (double)e11;
#pragma unroll
  for (int o = 1; o < 32; o <<= 1){
    const double v0 = __shfl_up_sync(0xffffffffu, sc0, o);
    const double v1 = __shfl_up_sync(0xffffffffu, sc1, o);
    if (lane >= o){ sc0 += v0; sc1 += v1; }
  }
  if (lane == 31){ s_w0[w] = sc0; s_w1[w] = sc1; }
  __syncthreads();
  if (w == 0 && lane < 8){
    double v0 = s_w0[lane], v1 = s_w1[lane];
#pragma unroll
    for (int o = 1; o < 8; o <<= 1){
      const double u0 = __shfl_up_sync(0xffu, v0, o);
      const double u1 = __shfl_up_sync(0xffu, v1, o);
      if (lane >= o){ v0 += u0; v1 += u1; }
    }
    s_w0[lane] = v0; s_w1[lane] = v1;
  }
  __syncthreads();
  const double wo0 = (w > 0) ? s_w0[w - 1] : 0.0;
  const double wo1 = (w > 0) ? s_w1[w - 1] : 0.0;
  const double q0 = wo0 + sc0, q1 = wo1 + sc1;
  s_P0[x0] = q0 - (double)e01;  s_P0[x1] = q0;
  s_P1[x0] = q1 - (double)e11;  s_P1[x1] = q1;
  __syncthreads();
  const double total0 = s_P0[N - 1], total1 = s_P1[N - 1];

  // il: first sorted pos with Ls >= li (label-only; shared by both rows)
  int lo = 0, len = N;
  while (len){ const int h = len >> 1, m = lo + h;
    if (s_Ls[m] < li){ lo = m + 1; len -= h + 1; } else len = h; }
  const int il = lo;

  // 2 k's per thread; boundaries shared by both rows
  const int k0 = t, k1 = t + 256;
  const float tk0 = fabsf(s_lab[k0] - li);      // k0 < 256
  const float tk1 = fabsf(s_lab[k1 & 255] - li);
  int a0 = 0, la0 = il + 1, c0 = il, lc0 = N - il;
  int a1 = 0, la1 = il + 1, c1 = il, lc1 = N - il;
#pragma unroll 1
  for (int s = 0; s < 10; s++){
    if (la0){ const int h = la0 >> 1, m = a0 + h;
      if (!(fabsf(s_Ls[m] - li) < tk0)){ a0 = m + 1; la0 -= h + 1; } else la0 = h; }
    if (lc0){ const int h = lc0 >> 1, m = c0 + h;
      if ( (fabsf(s_Ls[m] - li) < tk0)){ c0 = m + 1; lc0 -= h + 1; } else lc0 = h; }
    if (la1){ const int h = la1 >> 1, m = a1 + h;
      if (!(fabsf(s_Ls[m] - li) < tk1)){ a1 = m + 1; la1 -= h + 1; } else la1 = h; }
    if (lc1){ const int h = lc1 >> 1, m = c1 + h;
      if ( (fabsf(s_Ls[m] - li) < tk1)){ c1 = m + 1; lc1 -= h + 1; } else lc1 = h; }
  }

  float lgsum = 0.f;
  // row i0
  if (k0 != i0){
    const double neg = (tk0 == 0.f) ? (total0 - 1.0)
        : (total0 - (s_P0[c0 - 1] - (a0 > 0 ? s_P0[a0 - 1] : 0.0)));
    lgsum += lg2_ap((float)neg);
  }
  if (k1 != i0){   // always true (k1 >= 256 > i0)
    const double neg = (tk1 == 0.f) ? (total0 - 1.0)
        : (total0 - (s_P0[c1 - 1] - (a1 > 0 ? s_P0[a1 - 1] : 0.0)));
    lgsum += lg2_ap((float)neg);
  }
  // row i1
  if (k0 != i1){   // always true
    const double neg = (tk0 == 0.f) ? (total1 - 1.0)
        : (total1 - (s_P1[c0 - 1] - (a0 > 0 ? s_P1[a0 - 1] : 0.0)));
    lgsum += lg2_ap((float)neg);
  }
  if (k1 != i1){
    const double neg = (tk1 == 0.f) ? (total1 - 1.0)
        : (total1 - (s_P1[c1 - 1] - (a1 > 0 ? s_P1[a1 - 1] : 0.0)));
    lgsum += lg2_ap((float)neg);
  }

  const float dsum = (d00 + d01) + (d10 + d11);
  double acc = 0.5 * (double)dsum + (double)(LN2 * lgsum);

#pragma unroll
  for (int o = 16; o; o >>= 1) acc += __shfl_xor_sync(0xffffffffu, acc, o);
  if (lane == 0) s_red[w] = acc;
  __syncthreads();
  if (w == 0){
    double v = (lane < 8) ? s_red[lane] : 0.0;
#pragma unroll
    for (int o = 4; o; o >>= 1) v += __shfl_xor_sync(0xffffffffu, v, o);
    if (lane == 0){
      g_partial[blockIdx.x] = v;
      __threadfence();
      s_last = (atomicAdd(&g_count, 1u) == 255u);
    }
  }
  __syncthreads();

  if (s_last){
    double v = *((volatile double*)&g_partial[t]);
#pragma unroll
    for (int o = 16; o; o >>= 1) v += __shfl_xor_sync(0xffffffffu, v, o);
    if (lane == 0) s_red[w] = v;
    __syncthreads();
    if (w == 0){
      double s = (lane < 8) ? s_red[lane] : 0.0;
#pragma unroll
      for (int o = 4; o; o >>= 1) s += __shfl_xor_sync(0xffffffffu, s, o);
      if (lane == 0){
        out[0] = (float)(s / (512.0 * 511.0));
        g_count = 0;
      }
    }
  }
}

extern "C" void kernel_launch(void* const* d_in, const int* in_sizes, int n_in,
                              void* d_out, int out_size)
{
  const float* feat   = (const float*)d_in[0];
  const float* labels = (const float*)d_in[1];
  float* out = (float*)d_out;

  cudaFuncSetAttribute(dist_kernel, cudaFuncAttributeMaxDynamicSharedMemorySize,
                       (int)sizeof(GSmem));
  dist_kernel<<<256, 256, sizeof(GSmem)>>>(feat, labels);
  loss_kernel<<<256, 256>>>(labels, out);
}